// round 10
// baseline (speedup 1.0000x reference)
#include <cuda_runtime.h>

// SKA_Small: out[b,g,cg,h,w] = sum_{3x3 taps} x[b,g,cg,h+ki-1,w+kj-1] * w[b,g,ki*3+kj,h,w]
// x: [8,64,128,128] f32, w: [8,8,1,9,128,128] f32, out like x.
//
// R7: tap-outer / channel-inner. Per tap-row ki, load 3 w vectors (12 regs),
// then 8 INDEPENDENT x loads (one per channel) feed 8 independent accumulator
// chains -> MLP ~8 (was ~3). w still read once chip-wide; same total loads.
// 2 items per warp -> 4096 warps = one fully-resident wave at 64 regs.

constexpr int B = 8, C = 64, H = 128, W = 128, G = 8, CG = 8;
constexpr int HW = H * W;
constexpr int ITEMS = (B * G) * H;   // 8192 warp-rows
constexpr int WARPS = ITEMS / 2;     // 4096 warps

__global__ __launch_bounds__(256, 4) void ska_small_kernel(
    const float* __restrict__ x,
    const float* __restrict__ w,
    float* __restrict__ out)
{
    const int lane  = threadIdx.x & 31;
    const int warp0 = (blockIdx.x * 256 + threadIdx.x) >> 5;  // 0..4095
    const int w0    = lane * 4;

    #pragma unroll
    for (int it = 0; it < 2; it++) {
        const int item = warp0 + it * WARPS;   // 0..8191
        const int h    = item & 127;
        const int bg   = item >> 7;            // b*G + g

        const bool hm = (h > 0);
        const bool hp = (h < H - 1);

        const float* wbp = w + (bg * 9) * HW + h * W + w0;
        const float* xb  = x + (bg * CG) * HW + h * W + w0;

        float4 acc[CG];
        #pragma unroll
        for (int c = 0; c < CG; c++) acc[c] = make_float4(0.f, 0.f, 0.f, 0.f);

        #pragma unroll
        for (int ki = 0; ki < 3; ki++) {
            const int  dh = ki - 1;
            const bool rv = (dh == 0) | (dh < 0 ? hm : hp);

            // this tap-row's 3 weight vectors (shared by all 8 channels)
            const float4 wa = *(const float4*)(wbp + (ki * 3 + 0) * HW);  // x[w-1]
            const float4 wm = *(const float4*)(wbp + (ki * 3 + 1) * HW);  // x[w]
            const float4 wc = *(const float4*)(wbp + (ki * 3 + 2) * HW);  // x[w+1]

            #pragma unroll
            for (int c = 0; c < CG; c++) {
                const float4 v = rv ? *(const float4*)(xb + c * HW + dh * W)
                                    : make_float4(0.f, 0.f, 0.f, 0.f);
                float l = __shfl_up_sync(0xffffffffu, v.w, 1);
                float r = __shfl_down_sync(0xffffffffu, v.x, 1);
                if (lane == 0)  l = 0.f;
                if (lane == 31) r = 0.f;

                float4 a = acc[c];
                a.x = fmaf(wa.x, l,   fmaf(wm.x, v.x, fmaf(wc.x, v.y, a.x)));
                a.y = fmaf(wa.y, v.x, fmaf(wm.y, v.y, fmaf(wc.y, v.z, a.y)));
                a.z = fmaf(wa.z, v.y, fmaf(wm.z, v.z, fmaf(wc.z, v.w, a.z)));
                a.w = fmaf(wa.w, v.z, fmaf(wm.w, v.w, fmaf(wc.w, r,   a.w)));
                acc[c] = a;
            }
        }

        float* ob = out + (bg * CG) * HW + h * W + w0;
        #pragma unroll
        for (int c = 0; c < CG; c++)
            *(float4*)(ob + c * HW) = acc[c];
    }
}

extern "C" void kernel_launch(void* const* d_in, const int* in_sizes, int n_in,
                              void* d_out, int out_size)
{
    const float* x = (const float*)d_in[0];
    const float* w = (const float*)d_in[1];
    float* out = (float*)d_out;

    // 4096 warps = 512 blocks x 256 threads; 4 blocks/SM -> single wave
    ska_small_kernel<<<WARPS * 32 / 256, 256>>>(x, w, out);
}